// round 1
// baseline (speedup 1.0000x reference)
#include <cuda_runtime.h>
#include <cuda_bf16.h>

// PreProcesser: backbone frames + electrostatic field voxel divergence.
// Shapes fixed by the problem: Z=2, N=256 (ZN=512 residues), A=14 atoms,
// AA=21 residue types, voxel 16x16x16, RES=1, X_LBL=20.
//
// Output layout (tuple flattened in return order):
//   C_backbone (Z,N,4,3)        : 512*12   = 6144 floats   at offset 0
//   divergence (Z,N,1,16,16,16) : 512*4096 = 2097152 floats at offset 6144
//   frames     (Z,N,3,3)        : 512*9    = 4608 floats    at offset 2103296

#define A_ 14

__global__ __launch_bounds__(512, 2)
void preproc_kernel(const float* __restrict__ C,
                    const int*   __restrict__ L32,
                    const float* __restrict__ atom_mask,
                    const float* __restrict__ amber,
                    float* __restrict__ out,
                    int zn)
{
    float* out_cb  = out;                      // zn*12
    float* out_div = out + (size_t)zn * 12;    // zn*4096
    float* out_fr  = out_div + (size_t)zn * 4096; // zn*9

    __shared__ float  sS[4096];      // fx+fy+fz per voxel
    __shared__ float  sTail[512];    // fx at x=14 (first 256) and x=15 (last 256)
    __shared__ float4 sAtom[A_];     // (ax, ay, az, charge)
    __shared__ float  sFrm[12];      // x_unit, y_unit, z_unit, origin(=cb)
    __shared__ int    sLc;

    const int res = blockIdx.x;
    const int tid = threadIdx.x;

    // ---- label load with int64/int32 dtype auto-detection (bounds-safe) ----
    if (tid == 32) {
        // If L is int64 (little endian), every odd 32-bit word is the high
        // word of a value in [-1, 21) -> must be 0 or -1. With random int32
        // labels in [0,21) the odd words are labels (virtually never all 0/-1).
        bool maybe64 = true;
        for (int k = 1; k < 2 * 256; k += 2) {      // reads <= 512 int32s: safe either way
            int v = L32[k];
            if (v != 0 && v != -1) { maybe64 = false; break; }
        }
        long long l;
        if (maybe64) l = ((const long long*)L32)[res];
        else         l = (long long)L32[res];
        sLc = (l == -1) ? 20 : (int)l;   // X_LBL = 20
    }

    // ---- per-residue backbone + frames (thread 0) ----
    if (tid == 0) {
        const float* Cr = C + (size_t)res * (A_ * 3);
        float nx=Cr[0],  ny=Cr[1],  nz=Cr[2];
        float cax=Cr[3], cay=Cr[4], caz=Cr[5];
        float cx=Cr[6],  cy=Cr[7],  cz=Cr[8];

        float b1x=cax-nx,  b1y=cay-ny,  b1z=caz-nz;
        float b2x=cx-cax,  b2y=cy-cay,  b2z=cz-caz;
        float b3x=b1y*b2z-b1z*b2y;
        float b3y=b1z*b2x-b1x*b2z;
        float b3z=b1x*b2y-b1y*b2x;
        float cbx = cax - 0.58273431f*b2x + 0.56802827f*b1x - 0.54067466f*b3x;
        float cby = cay - 0.58273431f*b2y + 0.56802827f*b1y - 0.54067466f*b3y;
        float cbz = caz - 0.58273431f*b2z + 0.56802827f*b1z - 0.54067466f*b3z;

        // y = cb - ca
        float yx=cbx-cax, yy=cby-cay, yz=cbz-caz;
        float yn = sqrtf(yx*yx + yy*yy + yz*yz);
        float yd = fmaxf(yn, 1e-6f);
        float yux=yx/yd, yuy=yy/yd, yuz=yz/yd;

        // x_raw = c - n;  NOTE: reference subtracts the SCALAR projection
        // from every component (bug-compatible).
        float xrx=cx-nx, xry=cy-ny, xrz=cz-nz;
        float xp = xrx*yux + xry*yuy + xrz*yuz;
        float xx=xrx-xp, xy=xry-xp, xz=xrz-xp;
        float xn = sqrtf(xx*xx + xy*xy + xz*xz);
        float xd = fmaxf(xn, 1e-6f);
        float xux=xx/xd, xuy=xy/xd, xuz=xz/xd;

        // z = cross(x_unit, y_unit)
        float zux = xuy*yuz - xuz*yuy;
        float zuy = xuz*yux - xux*yuz;
        float zuz = xux*yuy - xuy*yux;

        float* cbp = out_cb + (size_t)res * 12;
        cbp[0]=nx;  cbp[1]=ny;  cbp[2]=nz;
        cbp[3]=cax; cbp[4]=cay; cbp[5]=caz;
        cbp[6]=cx;  cbp[7]=cy;  cbp[8]=cz;
        cbp[9]=cbx; cbp[10]=cby; cbp[11]=cbz;

        float* frp = out_fr + (size_t)res * 9;
        frp[0]=xux; frp[1]=xuy; frp[2]=xuz;
        frp[3]=yux; frp[4]=yuy; frp[5]=yuz;
        frp[6]=zux; frp[7]=zuy; frp[8]=zuz;

        sFrm[0]=xux; sFrm[1]=xuy; sFrm[2]=xuz;
        sFrm[3]=yux; sFrm[4]=yuy; sFrm[5]=yuz;
        sFrm[6]=zux; sFrm[7]=zuy; sFrm[8]=zuz;
        sFrm[9]=cbx; sFrm[10]=cby; sFrm[11]=cbz;   // origin = cb
    }
    __syncthreads();

    if (tid < A_) {
        const float* Cr = C + (size_t)res * (A_ * 3) + tid * 3;
        float q = amber[sLc * A_ + tid] * atom_mask[(size_t)res * A_ + tid];
        sAtom[tid] = make_float4(Cr[0], Cr[1], Cr[2], q);
    }
    __syncthreads();

    const float xux=sFrm[0], xuy=sFrm[1], xuz=sFrm[2];
    const float yux=sFrm[3], yuy=sFrm[4], yuz=sFrm[5];
    const float zux=sFrm[6], zuy=sFrm[7], zuz=sFrm[8];
    const float ox =sFrm[9], oy =sFrm[10], oz =sFrm[11];

    // ---- field per voxel: 8 voxels/thread ----
    #pragma unroll
    for (int it = 0; it < 8; it++) {
        int i = tid + it * 512;
        int x = i >> 8, y = (i >> 4) & 15, v = i & 15;
        float gx = (float)x - 8.0f;
        float gy = (float)y - 4.0f;
        float gz = (float)v - 8.0f;
        // local voxel position: origin + gx*x_unit + gy*y_unit + gz*z_unit
        float px = ox + gx*xux + gy*yux + gz*zux;
        float py = oy + gx*xuy + gy*yuy + gz*zuy;
        float pz = oz + gx*xuz + gy*yuz + gz*zuz;

        float fx=0.f, fy=0.f, fz=0.f;
        #pragma unroll
        for (int a = 0; a < A_; a++) {
            float4 at = sAtom[a];
            float dx = px - at.x, dy = py - at.y, dz = pz - at.z;
            float d2 = fmaf(dx, dx, fmaf(dy, dy, dz * dz));
            // dist_term factor:
            //   d >= 1 : vec / d^3  -> rsqrt(d2)^3
            //   0<d<1  : vec / d    -> rsqrt(d2)
            //   d == 0 : 0
            float r = rsqrtf(d2);
            r = r * fmaf(-0.5f * d2, r * r, 1.5f);    // one Newton step
            float f3 = r * r * r;
            float f  = (d2 >= 1.0f) ? f3 : r;
            f = (d2 > 0.0f) ? f * at.w : 0.0f;        // guards NaN at d2==0
            fx = fmaf(dx, f, fx);
            fy = fmaf(dy, f, fy);
            fz = fmaf(dz, f, fz);
        }

        // normalize field (leave zero vector untouched, like reference)
        float fn2 = fmaf(fx, fx, fmaf(fy, fy, fz * fz));
        if (fn2 > 0.f) {
            float rn = rsqrtf(fn2);
            rn = rn * fmaf(-0.5f * fn2, rn * rn, 1.5f);
            fx *= rn; fy *= rn; fz *= rn;
        }

        sS[i] = fx + fy + fz;
        if (x >= 14) sTail[((x - 14) << 8) | (i & 255)] = fx;
    }
    __syncthreads();

    // ---- divergence: all three components are differenced along voxel-x,
    // with sign flips for the y/z components at the last plane. ----
    float* od = out_div + (size_t)res * 4096;
    #pragma unroll
    for (int it = 0; it < 8; it++) {
        int i = tid + it * 512;
        int x = i >> 8;
        float d;
        if (x == 0) {
            d = sS[i + 256] - sS[i];
        } else if (x == 15) {
            int yv = i & 255;
            // (fx15-fx14) + (fy14-fy15) + (fz14-fz15)
            //   = 2*(fx15-fx14) + S14 - S15
            d = 2.0f * (sTail[256 + yv] - sTail[yv]) + sS[i - 256] - sS[i];
        } else {
            d = 0.5f * (sS[i + 256] - sS[i - 256]);
        }
        od[i] = d;
    }
}

extern "C" void kernel_launch(void* const* d_in, const int* in_sizes, int n_in,
                              void* d_out, int out_size) {
    const float* C     = (const float*)d_in[0];   // (Z,N,14,3) f32
    const int*   L     = (const int*)d_in[1];     // (Z,N) int64-or-int32 (auto-detected)
    const float* amask = (const float*)d_in[2];   // (Z,N,14) f32
    // d_in[3] = valid_mask (unused by reference)
    const float* amber = (const float*)d_in[4];   // (21,14) f32
    int zn = in_sizes[1];                         // Z*N = 512
    preproc_kernel<<<zn, 512>>>(C, L, amask, amber, (float*)d_out, zn);
}